// round 15
// baseline (speedup 1.0000x reference)
#include <cuda_runtime.h>
#include <cuda_bf16.h>
#include <cstdint>

#define NN 50000
#define NE 800000
#define D  128
#define KH 3
#define NB   ((NN + 255) / 256)

// ---------------- scratch ----------------
__device__ int   g_deg[NN];          // zero on entry (zero-init + tail reset in scatter)
__device__ float g_dinv[NN];
__device__ int   g_rowptr[NN + 1];
__device__ int   g_cursor[NN];
__device__ int   g_col[NE];
__device__ float g_val[NE];
__device__ volatile int g_flag[NB];  // zero on entry
__device__ int   g_agg[NB];
__device__ int   g_inc[NB];
__device__ float g_H[2][2][(size_t)NN * D];
__device__ __nv_bfloat16 g_Chi[2][(size_t)NN * 256];
__device__ __nv_bfloat16 g_Clo[2][(size_t)NN * 256];
__device__ __nv_bfloat16 g_Bp[2][128 * 768];

// ---------------- helpers ----------------
__device__ __forceinline__ uint32_t smem_u32(const void* p) {
    uint32_t a;
    asm("{ .reg .u64 t; cvta.to.shared.u64 t, %1; cvt.u32.u64 %0, t; }" : "=r"(a) : "l"(p));
    return a;
}
// gather load with L1 retain-priority hint (X rows are reused ~deg times)
__device__ __forceinline__ float4 ldg_el(const float* p) {
    float4 v;
    asm("ld.global.nc.L1::evict_last.v4.f32 {%0,%1,%2,%3}, [%4];"
        : "=f"(v.x), "=f"(v.y), "=f"(v.z), "=f"(v.w) : "l"(p));
    return v;
}
__device__ __forceinline__ void ldsm4(uint32_t* r, uint32_t addr) {
    asm volatile("ldmatrix.sync.aligned.m8n8.x4.shared.b16 {%0,%1,%2,%3}, [%4];"
                 : "=r"(r[0]), "=r"(r[1]), "=r"(r[2]), "=r"(r[3]) : "r"(addr));
}
__device__ __forceinline__ void ldsm2(uint32_t* r, uint32_t addr) {
    asm volatile("ldmatrix.sync.aligned.m8n8.x2.shared.b16 {%0,%1}, [%2];"
                 : "=r"(r[0]), "=r"(r[1]) : "r"(addr));
}
__device__ __forceinline__ void mma16816(float* d, const uint32_t* a, const uint32_t* b) {
    asm volatile(
        "mma.sync.aligned.m16n8k16.row.col.f32.bf16.bf16.f32 "
        "{%0,%1,%2,%3}, {%4,%5,%6,%7}, {%8,%9}, {%0,%1,%2,%3};"
        : "+f"(d[0]), "+f"(d[1]), "+f"(d[2]), "+f"(d[3])
        : "r"(a[0]), "r"(a[1]), "r"(a[2]), "r"(a[3]), "r"(b[0]), "r"(b[1]));
}
__device__ __forceinline__ void cp16(uint32_t dst, const void* src, int src_bytes) {
    asm volatile("cp.async.cg.shared.global [%0], [%1], 16, %2;"
                 :: "r"(dst), "l"(src), "r"(src_bytes));
}

// ---------------- count degrees ----------------
__global__ void k_count(const int* __restrict__ ei) {
    int e = blockIdx.x * blockDim.x + threadIdx.x;
    if (e < NE) atomicAdd(&g_deg[ei[e]], 1);
}

// ---------------- single-kernel scan (decoupled lookback) ----------------
__global__ void __launch_bounds__(256) k_scan() {
    __shared__ int s[256];
    __shared__ int s_base;
    int t   = threadIdx.x;
    int bid = blockIdx.x;
    int i   = bid * 256 + t;
    int d   = (i < NN) ? g_deg[i] : 0;
    if (i < NN) g_dinv[i] = (d > 0) ? rsqrtf((float)d) : 0.0f;

    s[t] = d;
    __syncthreads();
#pragma unroll
    for (int off = 1; off < 256; off <<= 1) {
        int u = (t >= off) ? s[t - off] : 0;
        __syncthreads();
        s[t] += u;
        __syncthreads();
    }
    int agg = s[255];

    if (t == 0) {
        if (bid == 0) {
            g_inc[0] = agg;
            __threadfence();
            g_flag[0] = 2;
            s_base = 0;
        } else {
            g_agg[bid] = agg;
            __threadfence();
            g_flag[bid] = 1;
            int base = 0;
            int p = bid - 1;
            while (p >= 0) {
                int f;
                do { f = g_flag[p]; } while (f == 0);
                __threadfence();
                if (f == 2) { base += g_inc[p]; break; }
                base += g_agg[p];
                p--;
            }
            g_inc[bid] = base + agg;
            __threadfence();
            g_flag[bid] = 2;
            s_base = base;
        }
    }
    __syncthreads();
    int base = s_base;
    if (i < NN) {
        g_cursor[i]     = base + s[t] - d;
        g_rowptr[i + 1] = base + s[t];
    }
    if (i == 0) g_rowptr[0] = 0;
}

// ---------------- scatter CSR + W hi/lo split + tail-reset deg/flags ----------------
__global__ void k_scatter_wsplit(const int* __restrict__ ei, const float* __restrict__ W) {
    int e = blockIdx.x * blockDim.x + threadIdx.x;
    if (e < NE) {
        int r = ei[e];
        int c = ei[NE + e];
        int p = atomicAdd(&g_cursor[r], 1);
        g_col[p] = c;
        g_val[p] = g_dinv[c];
    }
    if (e < 2 * 128 * 768) {
        int i   = e / (128 * 768);
        int rem = e % (128 * 768);
        int f   = rem / 768;
        int kp  = rem % 768;
        int seg = kp / 256;
        int k   = kp % 256;
        int j   = k / 128;
        int d   = k % 128;
        float w = W[(((size_t)(i * 2 + j) * 128 + d) * 128) + f];
        __nv_bfloat16 hi = __float2bfloat16_rn(w);
        __nv_bfloat16 v  = (seg == 1) ? __float2bfloat16_rn(w - __bfloat162float(hi)) : hi;
        g_Bp[i][(size_t)f * 768 + kp] = v;
    }
    if (e < NN) g_deg[e] = 0;
    if (e < NB) g_flag[e] = 0;
}

// ---------------- SpMM hops 0,1: one warp per (node, channel), 8-edge MLP ----------------
__global__ void __launch_bounds__(256) k_spmm(const float* __restrict__ x, int hop) {
    int gw   = (blockIdx.x * blockDim.x + threadIdx.x) >> 5;
    int lane = threadIdx.x & 31;
    if (gw >= 2 * NN) return;
    int chn  = (gw >= NN) ? 1 : 0;
    int node = gw - chn * NN;

    const float* X = (hop == 0) ? (x + (size_t)chn * NN * D) : g_H[0][chn];
    float*       Y = g_H[hop][chn];

    int s = g_rowptr[node];
    int e = g_rowptr[node + 1];

    float4 a = make_float4(0.f, 0.f, 0.f, 0.f);

    int i = s;
    for (; i + 8 <= e; i += 8) {
        int   c0 = g_col[i],     c1 = g_col[i + 1], c2 = g_col[i + 2], c3 = g_col[i + 3];
        int   c4 = g_col[i + 4], c5 = g_col[i + 5], c6 = g_col[i + 6], c7 = g_col[i + 7];
        float v0 = g_val[i],     v1 = g_val[i + 1], v2 = g_val[i + 2], v3 = g_val[i + 3];
        float v4 = g_val[i + 4], v5 = g_val[i + 5], v6 = g_val[i + 6], v7 = g_val[i + 7];
        float4 q0 = ldg_el(X + (size_t)c0 * D + lane * 4);
        float4 q1 = ldg_el(X + (size_t)c1 * D + lane * 4);
        float4 q2 = ldg_el(X + (size_t)c2 * D + lane * 4);
        float4 q3 = ldg_el(X + (size_t)c3 * D + lane * 4);
        float4 q4 = ldg_el(X + (size_t)c4 * D + lane * 4);
        float4 q5 = ldg_el(X + (size_t)c5 * D + lane * 4);
        float4 q6 = ldg_el(X + (size_t)c6 * D + lane * 4);
        float4 q7 = ldg_el(X + (size_t)c7 * D + lane * 4);
        a.x += v0 * q0.x; a.y += v0 * q0.y; a.z += v0 * q0.z; a.w += v0 * q0.w;
        a.x += v1 * q1.x; a.y += v1 * q1.y; a.z += v1 * q1.z; a.w += v1 * q1.w;
        a.x += v2 * q2.x; a.y += v2 * q2.y; a.z += v2 * q2.z; a.w += v2 * q2.w;
        a.x += v3 * q3.x; a.y += v3 * q3.y; a.z += v3 * q3.z; a.w += v3 * q3.w;
        a.x += v4 * q4.x; a.y += v4 * q4.y; a.z += v4 * q4.z; a.w += v4 * q4.w;
        a.x += v5 * q5.x; a.y += v5 * q5.y; a.z += v5 * q5.z; a.w += v5 * q5.w;
        a.x += v6 * q6.x; a.y += v6 * q6.y; a.z += v6 * q6.z; a.w += v6 * q6.w;
        a.x += v7 * q7.x; a.y += v7 * q7.y; a.z += v7 * q7.z; a.w += v7 * q7.w;
    }
    for (; i + 4 <= e; i += 4) {
        int   c0 = g_col[i],  c1 = g_col[i + 1], c2 = g_col[i + 2], c3 = g_col[i + 3];
        float v0 = g_val[i],  v1 = g_val[i + 1], v2 = g_val[i + 2], v3 = g_val[i + 3];
        float4 q0 = ldg_el(X + (size_t)c0 * D + lane * 4);
        float4 q1 = ldg_el(X + (size_t)c1 * D + lane * 4);
        float4 q2 = ldg_el(X + (size_t)c2 * D + lane * 4);
        float4 q3 = ldg_el(X + (size_t)c3 * D + lane * 4);
        a.x += v0 * q0.x; a.y += v0 * q0.y; a.z += v0 * q0.z; a.w += v0 * q0.w;
        a.x += v1 * q1.x; a.y += v1 * q1.y; a.z += v1 * q1.z; a.w += v1 * q1.w;
        a.x += v2 * q2.x; a.y += v2 * q2.y; a.z += v2 * q2.z; a.w += v2 * q2.w;
        a.x += v3 * q3.x; a.y += v3 * q3.y; a.z += v3 * q3.z; a.w += v3 * q3.w;
    }
    for (; i < e; i++) {
        int   c0 = g_col[i];
        float v0 = g_val[i];
        float4 q0 = ldg_el(X + (size_t)c0 * D + lane * 4);
        a.x += v0 * q0.x; a.y += v0 * q0.y; a.z += v0 * q0.z; a.w += v0 * q0.w;
    }

    float sc = g_dinv[node];
    a.x *= sc; a.y *= sc; a.z *= sc; a.w *= sc;
    ((float4*)(Y + (size_t)node * D))[lane] = a;
}

// ---------------- hop-2 SpMM + combine: one warp per (node, channel), 8-edge MLP ----------------
__device__ __forceinline__ void store_hilo(__nv_bfloat16* hi_p, __nv_bfloat16* lo_p, float4 r) {
    __nv_bfloat16 h0 = __float2bfloat16_rn(r.x);
    __nv_bfloat16 h1 = __float2bfloat16_rn(r.y);
    __nv_bfloat16 h2 = __float2bfloat16_rn(r.z);
    __nv_bfloat16 h3 = __float2bfloat16_rn(r.w);
    __nv_bfloat16 l0 = __float2bfloat16_rn(r.x - __bfloat162float(h0));
    __nv_bfloat16 l1 = __float2bfloat16_rn(r.y - __bfloat162float(h1));
    __nv_bfloat16 l2 = __float2bfloat16_rn(r.z - __bfloat162float(h2));
    __nv_bfloat16 l3 = __float2bfloat16_rn(r.w - __bfloat162float(h3));
    __nv_bfloat162 hp0(h0, h1), hp1(h2, h3), lp0(l0, l1), lp1(l2, l3);
    ((__nv_bfloat162*)hi_p)[0] = hp0; ((__nv_bfloat162*)hi_p)[1] = hp1;
    ((__nv_bfloat162*)lo_p)[0] = lp0; ((__nv_bfloat162*)lo_p)[1] = lp1;
}

__global__ void __launch_bounds__(256) k_spmm_combine(const float* __restrict__ x, const float* __restrict__ params) {
    int gw   = (blockIdx.x * blockDim.x + threadIdx.x) >> 5;
    int lane = threadIdx.x & 31;
    if (gw >= 2 * NN) return;
    int j    = (gw >= NN) ? 1 : 0;     // input channel
    int node = gw - j * NN;

    const float* X = g_H[1][j];

    int s = g_rowptr[node];
    int e = g_rowptr[node + 1];

    float4 a = make_float4(0.f, 0.f, 0.f, 0.f);

    int i = s;
    for (; i + 8 <= e; i += 8) {
        int   c0 = g_col[i],     c1 = g_col[i + 1], c2 = g_col[i + 2], c3 = g_col[i + 3];
        int   c4 = g_col[i + 4], c5 = g_col[i + 5], c6 = g_col[i + 6], c7 = g_col[i + 7];
        float v0 = g_val[i],     v1 = g_val[i + 1], v2 = g_val[i + 2], v3 = g_val[i + 3];
        float v4 = g_val[i + 4], v5 = g_val[i + 5], v6 = g_val[i + 6], v7 = g_val[i + 7];
        float4 q0 = ldg_el(X + (size_t)c0 * D + lane * 4);
        float4 q1 = ldg_el(X + (size_t)c1 * D + lane * 4);
        float4 q2 = ldg_el(X + (size_t)c2 * D + lane * 4);
        float4 q3 = ldg_el(X + (size_t)c3 * D + lane * 4);
        float4 q4 = ldg_el(X + (size_t)c4 * D + lane * 4);
        float4 q5 = ldg_el(X + (size_t)c5 * D + lane * 4);
        float4 q6 = ldg_el(X + (size_t)c6 * D + lane * 4);
        float4 q7 = ldg_el(X + (size_t)c7 * D + lane * 4);
        a.x += v0 * q0.x; a.y += v0 * q0.y; a.z += v0 * q0.z; a.w += v0 * q0.w;
        a.x += v1 * q1.x; a.y += v1 * q1.y; a.z += v1 * q1.z; a.w += v1 * q1.w;
        a.x += v2 * q2.x; a.y += v2 * q2.y; a.z += v2 * q2.z; a.w += v2 * q2.w;
        a.x += v3 * q3.x; a.y += v3 * q3.y; a.z += v3 * q3.z; a.w += v3 * q3.w;
        a.x += v4 * q4.x; a.y += v4 * q4.y; a.z += v4 * q4.z; a.w += v4 * q4.w;
        a.x += v5 * q5.x; a.y += v5 * q5.y; a.z += v5 * q5.z; a.w += v5 * q5.w;
        a.x += v6 * q6.x; a.y += v6 * q6.y; a.z += v6 * q6.z; a.w += v6 * q6.w;
        a.x += v7 * q7.x; a.y += v7 * q7.y; a.z += v7 * q7.z; a.w += v7 * q7.w;
    }
    for (; i + 4 <= e; i += 4) {
        int   c0 = g_col[i],  c1 = g_col[i + 1], c2 = g_col[i + 2], c3 = g_col[i + 3];
        float v0 = g_val[i],  v1 = g_val[i + 1], v2 = g_val[i + 2], v3 = g_val[i + 3];
        float4 q0 = ldg_el(X + (size_t)c0 * D + lane * 4);
        float4 q1 = ldg_el(X + (size_t)c1 * D + lane * 4);
        float4 q2 = ldg_el(X + (size_t)c2 * D + lane * 4);
        float4 q3 = ldg_el(X + (size_t)c3 * D + lane * 4);
        a.x += v0 * q0.x; a.y += v0 * q0.y; a.z += v0 * q0.z; a.w += v0 * q0.w;
        a.x += v1 * q1.x; a.y += v1 * q1.y; a.z += v1 * q1.z; a.w += v1 * q1.w;
        a.x += v2 * q2.x; a.y += v2 * q2.y; a.z += v2 * q2.z; a.w += v2 * q2.w;
        a.x += v3 * q3.x; a.y += v3 * q3.y; a.z += v3 * q3.z; a.w += v3 * q3.w;
    }
    for (; i < e; i++) {
        int   c0 = g_col[i];
        float v0 = g_val[i];
        float4 q0 = ldg_el(X + (size_t)c0 * D + lane * 4);
        a.x += v0 * q0.x; a.y += v0 * q0.y; a.z += v0 * q0.z; a.w += v0 * q0.w;
    }

    float sc = g_dinv[node];
    a.x *= sc; a.y *= sc; a.z *= sc; a.w *= sc;

    size_t hoff = (size_t)node * D;
    float4 h0 = __ldg((const float4*)(x + (size_t)j * NN * D + hoff) + lane);
    float4 h1 = *((const float4*)(g_H[0][j] + hoff) + lane);
    float4 h2 = *((const float4*)(g_H[1][j] + hoff) + lane);

#pragma unroll
    for (int ic = 0; ic < 2; ic++) {
        const float* p = params + (ic * 2 + j) * (KH + 1);
        float p0 = __ldg(p + 0), p1 = __ldg(p + 1), p2 = __ldg(p + 2), p3 = __ldg(p + 3);
        float4 r;
        r.x = p0 * h0.x + p1 * h1.x + p2 * h2.x + p3 * a.x;
        r.y = p0 * h0.y + p1 * h1.y + p2 * h2.y + p3 * a.y;
        r.z = p0 * h0.z + p1 * h1.z + p2 * h2.z + p3 * a.z;
        r.w = p0 * h0.w + p1 * h1.w + p2 * h2.w + p3 * a.w;
        size_t off = (size_t)node * 256 + j * 128 + lane * 4;
        store_hilo(&g_Chi[ic][off], &g_Clo[ic][off], r);
    }
}

// ---------------- big-tile mma.sync GEMM: M=256, N=128, KC=64 [r12 known-good] ----------------
#define KC   64
#define SST  72
#define NCHUNK 12
#define MT   256
#define NT_M2 ((NN + MT - 1) / MT)    // 196 M tiles
#define SA_STAGE (MT * SST)
#define SB_STAGE (128 * SST)
#define SMEM_BYTES ((2 * SA_STAGE + 2 * SB_STAGE) * 2)

__global__ void __launch_bounds__(256) k_gemm_mma(float* __restrict__ out) {
    extern __shared__ __nv_bfloat16 smem[];
    __nv_bfloat16* sA = smem;                    // [2][SA_STAGE]
    __nv_bfloat16* sB = smem + 2 * SA_STAGE;     // [2][SB_STAGE]

    const int ch = blockIdx.y;
    const int m0 = blockIdx.x * MT;

    int tid  = threadIdx.x;
    int wid  = tid >> 5;
    int lane = tid & 31;
    int wm   = (wid >> 1) * 64;      // 4 M-warp slots: 0,64,128,192
    int wn   = (wid & 1) * 64;       // 2 N-warp slots: 0,64

    const __nv_bfloat16* Bsrc = g_Bp[ch];

    auto load_stage = [&](int c, int st) {
        int seg = c >> 2;
        int kb  = (c & 3) * KC;
        const __nv_bfloat16* Asrc = (seg == 2) ? g_Clo[ch] : g_Chi[ch];
#pragma unroll
        for (int it = 0; it < 8; it++) {
            int u     = tid + it * 256;
            int row   = u >> 3;
            int inner = u & 7;
            uint32_t da = smem_u32(&sA[st * SA_STAGE + row * SST + inner * 8]);
            const void* ga = Asrc + (size_t)(m0 + row) * 256 + kb + inner * 8;
            cp16(da, ga, (m0 + row < NN) ? 16 : 0);
        }
#pragma unroll
        for (int it = 0; it < 4; it++) {
            int u     = tid + it * 256;
            int row   = u >> 3;
            int inner = u & 7;
            uint32_t db = smem_u32(&sB[st * SB_STAGE + row * SST + inner * 8]);
            const void* gb = Bsrc + (size_t)row * 768 + c * KC + inner * 8;
            cp16(db, gb, 16);
        }
        asm volatile("cp.async.commit_group;" ::: "memory");
    };

    float acc[4][8][4];
#pragma unroll
    for (int mt = 0; mt < 4; mt++)
#pragma unroll
        for (int nt = 0; nt < 8; nt++)
#pragma unroll
            for (int q = 0; q < 4; q++) acc[mt][nt][q] = 0.f;

    uint32_t aOffA = ((wm + (lane & 15)) * SST + (lane >> 4) * 8) * 2;
    uint32_t aOffB = ((wn + (lane & 7)) * SST + ((lane >> 3) & 1) * 8) * 2;

    load_stage(0, 0);

#pragma unroll 1
    for (int c = 0; c < NCHUNK; c++) {
        int st = c & 1;
        if (c + 1 < NCHUNK) {
            load_stage(c + 1, st ^ 1);
            asm volatile("cp.async.wait_group 1;" ::: "memory");
        } else {
            asm volatile("cp.async.wait_group 0;" ::: "memory");
        }
        __syncthreads();

        uint32_t aA = smem_u32(&sA[st * SA_STAGE]) + aOffA;
        uint32_t aB = smem_u32(&sB[st * SB_STAGE]) + aOffB;
#pragma unroll
        for (int ks = 0; ks < 4; ks++) {
            uint32_t af[4][4], bf4[8][2];
#pragma unroll
            for (int mt = 0; mt < 4; mt++)
                ldsm4(af[mt], aA + (mt * 16 * SST + ks * 16) * 2);
#pragma unroll
            for (int nt = 0; nt < 8; nt++)
                ldsm2(bf4[nt], aB + (nt * 8 * SST + ks * 16) * 2);
#pragma unroll
            for (int mt = 0; mt < 4; mt++)
#pragma unroll
                for (int nt = 0; nt < 8; nt++)
                    mma16816(acc[mt][nt], af[mt], bf4[nt]);
        }
        __syncthreads();
    }

    // epilogue
    float* Cout = out + (size_t)ch * NN * 128;
    int r0 = lane >> 2;
    int cn = (lane & 3) * 2;
#pragma unroll
    for (int mt = 0; mt < 4; mt++) {
        int gm_a = m0 + wm + mt * 16 + r0;
        int gm_b = gm_a + 8;
#pragma unroll
        for (int nt = 0; nt < 8; nt++) {
            int gn = wn + nt * 8 + cn;
            if (gm_a < NN)
                *(float2*)&Cout[(size_t)gm_a * 128 + gn] = make_float2(acc[mt][nt][0], acc[mt][nt][1]);
            if (gm_b < NN)
                *(float2*)&Cout[(size_t)gm_b * 128 + gn] = make_float2(acc[mt][nt][2], acc[mt][nt][3]);
        }
    }
}

// ---------------- launcher ----------------
extern "C" void kernel_launch(void* const* d_in, const int* in_sizes, int n_in,
                              void* d_out, int out_size) {
    const float* x      = (const float*)d_in[0];
    const int*   ei     = (const int*)  d_in[1];
    const float* W      = (const float*)d_in[2];
    const float* params = (const float*)d_in[3];
    float* out = (float*)d_out;

    static bool attr_set = false;
    if (!attr_set) {
        cudaFuncSetAttribute(k_gemm_mma, cudaFuncAttributeMaxDynamicSharedMemorySize, SMEM_BYTES);
        attr_set = true;
    }

    k_count         <<<(NE + 255) / 256, 256>>>(ei);
    k_scan          <<<NB, 256>>>();
    k_scatter_wsplit<<<(NE + 255) / 256, 256>>>(ei, W);

    k_spmm<<<(2 * NN * 32 + 255) / 256, 256>>>(x, 0);
    k_spmm<<<(2 * NN * 32 + 255) / 256, 256>>>(x, 1);
    k_spmm_combine<<<(2 * NN * 32 + 255) / 256, 256>>>(x, params);

    dim3 g(NT_M2, 2);
    k_gemm_mma<<<g, 256, SMEM_BYTES>>>(out);
}

// round 16
// speedup vs baseline: 1.0696x; 1.0696x over previous
#include <cuda_runtime.h>
#include <cuda_bf16.h>
#include <cstdint>

#define NN 50000
#define NE 800000
#define D  128
#define KH 3
#define NB   ((NN + 255) / 256)

// ---------------- scratch ----------------
__device__ int   g_deg[NN];          // zero on entry (zero-init + tail reset in scatter)
__device__ float g_dinv[NN];
__device__ int   g_rowptr[NN + 1];
__device__ int   g_cursor[NN];
__device__ int   g_col[NE];
__device__ float g_val[NE];
__device__ volatile int g_flag[NB];  // zero on entry
__device__ int   g_agg[NB];
__device__ int   g_inc[NB];
__device__ float g_H[2][2][(size_t)NN * D];
__device__ __nv_bfloat16 g_Chi[2][(size_t)NN * 256];
__device__ __nv_bfloat16 g_Clo[2][(size_t)NN * 256];
__device__ __nv_bfloat16 g_Bp[2][128 * 768];

// ---------------- helpers ----------------
__device__ __forceinline__ uint32_t smem_u32(const void* p) {
    uint32_t a;
    asm("{ .reg .u64 t; cvta.to.shared.u64 t, %1; cvt.u32.u64 %0, t; }" : "=r"(a) : "l"(p));
    return a;
}
__device__ __forceinline__ float4 ldg_el(const float* p) {
    float4 v;
    asm("ld.global.nc.L1::evict_last.v4.f32 {%0,%1,%2,%3}, [%4];"
        : "=f"(v.x), "=f"(v.y), "=f"(v.z), "=f"(v.w) : "l"(p));
    return v;
}
__device__ __forceinline__ void ldsm4(uint32_t* r, uint32_t addr) {
    asm volatile("ldmatrix.sync.aligned.m8n8.x4.shared.b16 {%0,%1,%2,%3}, [%4];"
                 : "=r"(r[0]), "=r"(r[1]), "=r"(r[2]), "=r"(r[3]) : "r"(addr));
}
__device__ __forceinline__ void ldsm2(uint32_t* r, uint32_t addr) {
    asm volatile("ldmatrix.sync.aligned.m8n8.x2.shared.b16 {%0,%1}, [%2];"
                 : "=r"(r[0]), "=r"(r[1]) : "r"(addr));
}
__device__ __forceinline__ void mma16816(float* d, const uint32_t* a, const uint32_t* b) {
    asm volatile(
        "mma.sync.aligned.m16n8k16.row.col.f32.bf16.bf16.f32 "
        "{%0,%1,%2,%3}, {%4,%5,%6,%7}, {%8,%9}, {%0,%1,%2,%3};"
        : "+f"(d[0]), "+f"(d[1]), "+f"(d[2]), "+f"(d[3])
        : "r"(a[0]), "r"(a[1]), "r"(a[2]), "r"(a[3]), "r"(b[0]), "r"(b[1]));
}
__device__ __forceinline__ void cp16(uint32_t dst, const void* src, int src_bytes) {
    asm volatile("cp.async.cg.shared.global [%0], [%1], 16, %2;"
                 :: "r"(dst), "l"(src), "r"(src_bytes));
}

// ---------------- count degrees ----------------
__global__ void k_count(const int* __restrict__ ei) {
    int e = blockIdx.x * blockDim.x + threadIdx.x;
    if (e < NE) atomicAdd(&g_deg[ei[e]], 1);
}

// ---------------- single-kernel scan (decoupled lookback) ----------------
__global__ void __launch_bounds__(256) k_scan() {
    __shared__ int s[256];
    __shared__ int s_base;
    int t   = threadIdx.x;
    int bid = blockIdx.x;
    int i   = bid * 256 + t;
    int d   = (i < NN) ? g_deg[i] : 0;
    if (i < NN) g_dinv[i] = (d > 0) ? rsqrtf((float)d) : 0.0f;

    s[t] = d;
    __syncthreads();
#pragma unroll
    for (int off = 1; off < 256; off <<= 1) {
        int u = (t >= off) ? s[t - off] : 0;
        __syncthreads();
        s[t] += u;
        __syncthreads();
    }
    int agg = s[255];

    if (t == 0) {
        if (bid == 0) {
            g_inc[0] = agg;
            __threadfence();
            g_flag[0] = 2;
            s_base = 0;
        } else {
            g_agg[bid] = agg;
            __threadfence();
            g_flag[bid] = 1;
            int base = 0;
            int p = bid - 1;
            while (p >= 0) {
                int f;
                do { f = g_flag[p]; } while (f == 0);
                __threadfence();
                if (f == 2) { base += g_inc[p]; break; }
                base += g_agg[p];
                p--;
            }
            g_inc[bid] = base + agg;
            __threadfence();
            g_flag[bid] = 2;
            s_base = base;
        }
    }
    __syncthreads();
    int base = s_base;
    if (i < NN) {
        g_cursor[i]     = base + s[t] - d;
        g_rowptr[i + 1] = base + s[t];
    }
    if (i == 0) g_rowptr[0] = 0;
}

// ---------------- scatter CSR + W hi/lo split + tail-reset deg/flags ----------------
__global__ void k_scatter_wsplit(const int* __restrict__ ei, const float* __restrict__ W) {
    int e = blockIdx.x * blockDim.x + threadIdx.x;
    if (e < NE) {
        int r = ei[e];
        int c = ei[NE + e];
        int p = atomicAdd(&g_cursor[r], 1);
        g_col[p] = c;
        g_val[p] = g_dinv[c];
    }
    if (e < 2 * 128 * 768) {
        int i   = e / (128 * 768);
        int rem = e % (128 * 768);
        int f   = rem / 768;
        int kp  = rem % 768;
        int seg = kp / 256;
        int k   = kp % 256;
        int j   = k / 128;
        int d   = k % 128;
        float w = W[(((size_t)(i * 2 + j) * 128 + d) * 128) + f];
        __nv_bfloat16 hi = __float2bfloat16_rn(w);
        __nv_bfloat16 v  = (seg == 1) ? __float2bfloat16_rn(w - __bfloat162float(hi)) : hi;
        g_Bp[i][(size_t)f * 768 + kp] = v;
    }
    if (e < NN) g_deg[e] = 0;
    if (e < NB) g_flag[e] = 0;
}

// ---------------- SpMM hops 0,1: one warp per (node, channel)  [r14 known-good] ----------------
__global__ void __launch_bounds__(256) k_spmm(const float* __restrict__ x, int hop) {
    int gw   = (blockIdx.x * blockDim.x + threadIdx.x) >> 5;
    int lane = threadIdx.x & 31;
    if (gw >= 2 * NN) return;
    int chn  = (gw >= NN) ? 1 : 0;
    int node = gw - chn * NN;

    const float* X = (hop == 0) ? (x + (size_t)chn * NN * D) : g_H[0][chn];
    float*       Y = g_H[hop][chn];

    int s = g_rowptr[node];
    int e = g_rowptr[node + 1];

    float4 a = make_float4(0.f, 0.f, 0.f, 0.f);

    int i = s;
    for (; i + 4 <= e; i += 4) {
        int   c0 = g_col[i],  c1 = g_col[i + 1], c2 = g_col[i + 2], c3 = g_col[i + 3];
        float v0 = g_val[i],  v1 = g_val[i + 1], v2 = g_val[i + 2], v3 = g_val[i + 3];
        float4 q0 = ldg_el(X + (size_t)c0 * D + lane * 4);
        float4 q1 = ldg_el(X + (size_t)c1 * D + lane * 4);
        float4 q2 = ldg_el(X + (size_t)c2 * D + lane * 4);
        float4 q3 = ldg_el(X + (size_t)c3 * D + lane * 4);
        a.x += v0 * q0.x; a.y += v0 * q0.y; a.z += v0 * q0.z; a.w += v0 * q0.w;
        a.x += v1 * q1.x; a.y += v1 * q1.y; a.z += v1 * q1.z; a.w += v1 * q1.w;
        a.x += v2 * q2.x; a.y += v2 * q2.y; a.z += v2 * q2.z; a.w += v2 * q2.w;
        a.x += v3 * q3.x; a.y += v3 * q3.y; a.z += v3 * q3.z; a.w += v3 * q3.w;
    }
    for (; i < e; i++) {
        int   c0 = g_col[i];
        float v0 = g_val[i];
        float4 q0 = ldg_el(X + (size_t)c0 * D + lane * 4);
        a.x += v0 * q0.x; a.y += v0 * q0.y; a.z += v0 * q0.z; a.w += v0 * q0.w;
    }

    float sc = g_dinv[node];
    a.x *= sc; a.y *= sc; a.z *= sc; a.w *= sc;
    ((float4*)(Y + (size_t)node * D))[lane] = a;
}

// ---------------- hop-2 SpMM + combine: one warp per (node, channel)  [r14 known-good] ----------------
__device__ __forceinline__ void store_hilo(__nv_bfloat16* hi_p, __nv_bfloat16* lo_p, float4 r) {
    __nv_bfloat16 h0 = __float2bfloat16_rn(r.x);
    __nv_bfloat16 h1 = __float2bfloat16_rn(r.y);
    __nv_bfloat16 h2 = __float2bfloat16_rn(r.z);
    __nv_bfloat16 h3 = __float2bfloat16_rn(r.w);
    __nv_bfloat16 l0 = __float2bfloat16_rn(r.x - __bfloat162float(h0));
    __nv_bfloat16 l1 = __float2bfloat16_rn(r.y - __bfloat162float(h1));
    __nv_bfloat16 l2 = __float2bfloat16_rn(r.z - __bfloat162float(h2));
    __nv_bfloat16 l3 = __float2bfloat16_rn(r.w - __bfloat162float(h3));
    __nv_bfloat162 hp0(h0, h1), hp1(h2, h3), lp0(l0, l1), lp1(l2, l3);
    ((__nv_bfloat162*)hi_p)[0] = hp0; ((__nv_bfloat162*)hi_p)[1] = hp1;
    ((__nv_bfloat162*)lo_p)[0] = lp0; ((__nv_bfloat162*)lo_p)[1] = lp1;
}

__global__ void __launch_bounds__(256) k_spmm_combine(const float* __restrict__ x, const float* __restrict__ params) {
    int gw   = (blockIdx.x * blockDim.x + threadIdx.x) >> 5;
    int lane = threadIdx.x & 31;
    if (gw >= 2 * NN) return;
    int j    = (gw >= NN) ? 1 : 0;     // input channel
    int node = gw - j * NN;

    const float* X = g_H[1][j];

    int s = g_rowptr[node];
    int e = g_rowptr[node + 1];

    float4 a = make_float4(0.f, 0.f, 0.f, 0.f);

    int i = s;
    for (; i + 4 <= e; i += 4) {
        int   c0 = g_col[i],  c1 = g_col[i + 1], c2 = g_col[i + 2], c3 = g_col[i + 3];
        float v0 = g_val[i],  v1 = g_val[i + 1], v2 = g_val[i + 2], v3 = g_val[i + 3];
        float4 q0 = ldg_el(X + (size_t)c0 * D + lane * 4);
        float4 q1 = ldg_el(X + (size_t)c1 * D + lane * 4);
        float4 q2 = ldg_el(X + (size_t)c2 * D + lane * 4);
        float4 q3 = ldg_el(X + (size_t)c3 * D + lane * 4);
        a.x += v0 * q0.x; a.y += v0 * q0.y; a.z += v0 * q0.z; a.w += v0 * q0.w;
        a.x += v1 * q1.x; a.y += v1 * q1.y; a.z += v1 * q1.z; a.w += v1 * q1.w;
        a.x += v2 * q2.x; a.y += v2 * q2.y; a.z += v2 * q2.z; a.w += v2 * q2.w;
        a.x += v3 * q3.x; a.y += v3 * q3.y; a.z += v3 * q3.z; a.w += v3 * q3.w;
    }
    for (; i < e; i++) {
        int   c0 = g_col[i];
        float v0 = g_val[i];
        float4 q0 = ldg_el(X + (size_t)c0 * D + lane * 4);
        a.x += v0 * q0.x; a.y += v0 * q0.y; a.z += v0 * q0.z; a.w += v0 * q0.w;
    }

    float sc = g_dinv[node];
    a.x *= sc; a.y *= sc; a.z *= sc; a.w *= sc;

    size_t hoff = (size_t)node * D;
    float4 h0 = __ldg((const float4*)(x + (size_t)j * NN * D + hoff) + lane);
    float4 h1 = *((const float4*)(g_H[0][j] + hoff) + lane);
    float4 h2 = *((const float4*)(g_H[1][j] + hoff) + lane);

#pragma unroll
    for (int ic = 0; ic < 2; ic++) {
        const float* p = params + (ic * 2 + j) * (KH + 1);
        float p0 = __ldg(p + 0), p1 = __ldg(p + 1), p2 = __ldg(p + 2), p3 = __ldg(p + 3);
        float4 r;
        r.x = p0 * h0.x + p1 * h1.x + p2 * h2.x + p3 * a.x;
        r.y = p0 * h0.y + p1 * h1.y + p2 * h2.y + p3 * a.y;
        r.z = p0 * h0.z + p1 * h1.z + p2 * h2.z + p3 * a.z;
        r.w = p0 * h0.w + p1 * h1.w + p2 * h2.w + p3 * a.w;
        size_t off = (size_t)node * 256 + j * 128 + lane * 4;
        store_hilo(&g_Chi[ic][off], &g_Clo[ic][off], r);
    }
}

// ---------------- A-reuse mma.sync GEMM: 8 super-chunks, A_hi shared by 2 B segments ----------------
#define KC   64
#define SST  72
#define MT   256
#define NT_M2 ((NN + MT - 1) / MT)    // 196 M tiles
#define SA_STAGE (MT * SST)
#define SB_STAGE (128 * SST)
// smem: sA[2][SA_STAGE] + sB0[2][SB_STAGE] + sB1[2][SB_STAGE]
#define SMEM_BYTES ((2 * SA_STAGE + 4 * SB_STAGE) * 2)
#define NSUPER 8

__global__ void __launch_bounds__(256) k_gemm_mma(float* __restrict__ out) {
    extern __shared__ __nv_bfloat16 smem[];
    __nv_bfloat16* sA  = smem;                                   // [2][SA_STAGE]
    __nv_bfloat16* sB0 = smem + 2 * SA_STAGE;                    // [2][SB_STAGE]
    __nv_bfloat16* sB1 = smem + 2 * SA_STAGE + 2 * SB_STAGE;     // [2][SB_STAGE]

    const int ch = blockIdx.y;
    const int m0 = blockIdx.x * MT;

    int tid  = threadIdx.x;
    int wid  = tid >> 5;
    int lane = tid & 31;
    int wm   = (wid >> 1) * 64;      // 4 M-warp slots
    int wn   = (wid & 1) * 64;       // 2 N-warp slots

    const __nv_bfloat16* Bsrc = g_Bp[ch];

    // super-chunk sc: sc<4 -> A=Chi[kc=sc], B0=block sc (seg0), B1=block sc+4 (seg1), 2 MMA passes
    //                sc>=4 -> A=Clo[kc=sc-4], B1=block sc+4 (seg2), 1 MMA pass
    auto load_stage = [&](int sc, int st) {
        bool dual = (sc < 4);
        int  kc   = dual ? sc : (sc - 4);
        int  kb   = kc * KC;
        const __nv_bfloat16* Asrc = dual ? g_Chi[ch] : g_Clo[ch];
#pragma unroll
        for (int it = 0; it < 8; it++) {
            int u     = tid + it * 256;
            int row   = u >> 3;
            int inner = u & 7;
            uint32_t da = smem_u32(&sA[st * SA_STAGE + row * SST + inner * 8]);
            const void* ga = Asrc + (size_t)(m0 + row) * 256 + kb + inner * 8;
            cp16(da, ga, (m0 + row < NN) ? 16 : 0);
        }
        int b1blk = sc + 4;
#pragma unroll
        for (int it = 0; it < 4; it++) {
            int u     = tid + it * 256;
            int row   = u >> 3;
            int inner = u & 7;
            uint32_t db1 = smem_u32(&sB1[st * SB_STAGE + row * SST + inner * 8]);
            const void* gb1 = Bsrc + (size_t)row * 768 + b1blk * KC + inner * 8;
            cp16(db1, gb1, 16);
        }
        if (dual) {
#pragma unroll
            for (int it = 0; it < 4; it++) {
                int u     = tid + it * 256;
                int row   = u >> 3;
                int inner = u & 7;
                uint32_t db0 = smem_u32(&sB0[st * SB_STAGE + row * SST + inner * 8]);
                const void* gb0 = Bsrc + (size_t)row * 768 + sc * KC + inner * 8;
                cp16(db0, gb0, 16);
            }
        }
        asm volatile("cp.async.commit_group;" ::: "memory");
    };

    float acc[4][8][4];
#pragma unroll
    for (int mt = 0; mt < 4; mt++)
#pragma unroll
        for (int nt = 0; nt < 8; nt++)
#pragma unroll
            for (int q = 0; q < 4; q++) acc[mt][nt][q] = 0.f;

    uint32_t aOffA = ((wm + (lane & 15)) * SST + (lane >> 4) * 8) * 2;
    uint32_t aOffB = ((wn + (lane & 7)) * SST + ((lane >> 3) & 1) * 8) * 2;

    load_stage(0, 0);

#pragma unroll 1
    for (int sc = 0; sc < NSUPER; sc++) {
        int st = sc & 1;
        if (sc + 1 < NSUPER) {
            load_stage(sc + 1, st ^ 1);
            asm volatile("cp.async.wait_group 1;" ::: "memory");
        } else {
            asm volatile("cp.async.wait_group 0;" ::: "memory");
        }
        __syncthreads();

        bool dual = (sc < 4);
        uint32_t aA  = smem_u32(&sA[st * SA_STAGE])  + aOffA;
        uint32_t aB0 = smem_u32(&sB0[st * SB_STAGE]) + aOffB;
        uint32_t aB1 = smem_u32(&sB1[st * SB_STAGE]) + aOffB;
#pragma unroll
        for (int ks = 0; ks < 4; ks++) {
            uint32_t af[4][4], bfr[8][2];
#pragma unroll
            for (int mt = 0; mt < 4; mt++)
                ldsm4(af[mt], aA + (mt * 16 * SST + ks * 16) * 2);
            // B1 pass (always)
#pragma unroll
            for (int nt = 0; nt < 8; nt++)
                ldsm2(bfr[nt], aB1 + (nt * 8 * SST + ks * 16) * 2);
#pragma unroll
            for (int mt = 0; mt < 4; mt++)
#pragma unroll
                for (int nt = 0; nt < 8; nt++)
                    mma16816(acc[mt][nt], af[mt], bfr[nt]);
            // B0 pass (reuses af) — only for hi super-chunks
            if (dual) {
#pragma unroll
                for (int nt = 0; nt < 8; nt++)
                    ldsm2(bfr[nt], aB0 + (nt * 8 * SST + ks * 16) * 2);
#pragma unroll
                for (int mt = 0; mt < 4; mt++)
#pragma unroll
                    for (int nt = 0; nt < 8; nt++)
                        mma16816(acc[mt][nt], af[mt], bfr[nt]);
            }
        }
        __syncthreads();
    }

    // epilogue
    float* Cout = out + (size_t)ch * NN * 128;
    int r0 = lane >> 2;
    int cn = (lane & 3) * 2;
#pragma unroll
    for (int mt = 0; mt < 4; mt++) {
        int gm_a = m0 + wm + mt * 16 + r0;
        int gm_b = gm_a + 8;
#pragma unroll
        for (int nt = 0; nt < 8; nt++) {
            int gn = wn + nt * 8 + cn;
            if (gm_a < NN)
                *(float2*)&Cout[(size_t)gm_a * 128 + gn] = make_float2(acc[mt][nt][0], acc[mt][nt][1]);
            if (gm_b < NN)
                *(float2*)&Cout[(size_t)gm_b * 128 + gn] = make_float2(acc[mt][nt][2], acc[mt][nt][3]);
        }
    }
}

// ---------------- launcher ----------------
extern "C" void kernel_launch(void* const* d_in, const int* in_sizes, int n_in,
                              void* d_out, int out_size) {
    const float* x      = (const float*)d_in[0];
    const int*   ei     = (const int*)  d_in[1];
    const float* W      = (const float*)d_in[2];
    const float* params = (const float*)d_in[3];
    float* out = (float*)d_out;

    static bool attr_set = false;
    if (!attr_set) {
        cudaFuncSetAttribute(k_gemm_mma, cudaFuncAttributeMaxDynamicSharedMemorySize, SMEM_BYTES);
        attr_set = true;
    }

    k_count         <<<(NE + 255) / 256, 256>>>(ei);
    k_scan          <<<NB, 256>>>();
    k_scatter_wsplit<<<(NE + 255) / 256, 256>>>(ei, W);

    k_spmm<<<(2 * NN * 32 + 255) / 256, 256>>>(x, 0);
    k_spmm<<<(2 * NN * 32 + 255) / 256, 256>>>(x, 1);
    k_spmm_combine<<<(2 * NN * 32 + 255) / 256, 256>>>(x, params);

    dim3 g(NT_M2, 2);
    k_gemm_mma<<<g, 256, SMEM_BYTES>>>(out);
}